// round 2
// baseline (speedup 1.0000x reference)
#include <cuda_runtime.h>
#include <math.h>

#define NN 50000
#define MM 1250000
#define H  64
#define EF 16
#define NIF 23
#define EWH 32

__device__ float g_hA[NN*H];
__device__ float g_hB[NN*H];
__device__ float g_hm[NN*H];
__device__ float g_agg[NN*H];
__device__ float g_Ad[NN*H];
__device__ float g_Bd[NN*H];
__device__ float g_alpha[MM];
__device__ int   g_src[MM];
__device__ int   g_dst[MM];
__device__ int2  g_csr[MM];
__device__ int   g_cnt[NN];
__device__ int   g_rowptr[NN+1];
__device__ int   g_cursor[NN];
__device__ int   g_is64;

__device__ __forceinline__ float sigf(float x){ return 1.f/(1.f+__expf(-x)); }

__global__ void k_zero(){
  int i = blockIdx.x*blockDim.x + threadIdx.x;
  if (i < NN) g_cnt[i] = 0;
}

__global__ void k_detect(const int* __restrict__ ei){
  __shared__ int nz;
  if (threadIdx.x == 0) nz = 0;
  __syncthreads();
  int c = 0;
  for (int i = threadIdx.x; i < 4096; i += blockDim.x) c += (ei[2*i+1] != 0);
  if (c) atomicAdd(&nz, 1);
  __syncthreads();
  if (threadIdx.x == 0) g_is64 = (nz == 0);
}

__global__ void k_prep(const void* __restrict__ ei, const float* __restrict__ ea,
                       const float* __restrict__ u,
                       const float* __restrict__ W1, const float* __restrict__ b1,
                       const float* __restrict__ W2, const float* __restrict__ b2){
  __shared__ float sW[EWH*EF], sb1[EWH], sW2[EWH], su[11], sb2;
  int t = threadIdx.x;
  for (int i = t; i < EWH*EF; i += blockDim.x) sW[i] = W1[i];
  if (t < EWH){ sb1[t] = b1[t]; sW2[t] = W2[t]; }
  if (t < 11) su[t] = u[t];
  if (t == 0) sb2 = b2[0];
  __syncthreads();
  int e = blockIdx.x*blockDim.x + t;
  if (e >= MM) return;
  int s, d;
  if (g_is64){
    const long long* p = (const long long*)ei;
    s = (int)p[e]; d = (int)p[MM + e];
  } else {
    const int* p = (const int*)ei;
    s = p[e]; d = p[MM + e];
  }
  g_src[e] = s; g_dst[e] = d;
  atomicAdd(&g_cnt[d], 1);
  float f[EF];
  #pragma unroll
  for (int k = 0; k < 5; k++) f[k] = ea[e*5 + k];
  #pragma unroll
  for (int k = 0; k < 11; k++) f[5+k] = su[k];
  float acc = sb2;
  #pragma unroll
  for (int i = 0; i < EWH; i++){
    float a = sb1[i];
    #pragma unroll
    for (int k = 0; k < EF; k++) a = fmaf(f[k], sW[i*EF + k], a);
    acc = fmaf(fmaxf(a, 0.f), sW2[i], acc);
  }
  g_alpha[e] = sigf(acc);
}

__global__ void k_scan(){
  __shared__ int sd[1024];
  __shared__ int carry;
  int t = threadIdx.x;
  if (t == 0){ carry = 0; g_rowptr[0] = 0; }
  __syncthreads();
  for (int base = 0; base < NN; base += 1024){
    int i = base + t;
    int v = (i < NN) ? g_cnt[i] : 0;
    sd[t] = v; __syncthreads();
    for (int off = 1; off < 1024; off <<= 1){
      int tmp = (t >= off) ? sd[t-off] : 0;
      __syncthreads();
      sd[t] += tmp;
      __syncthreads();
    }
    int incl = sd[t] + carry;
    if (i < NN){ g_rowptr[i+1] = incl; g_cursor[i] = incl - v; }
    __syncthreads();
    if (t == 1023) carry = incl;
    __syncthreads();
  }
}

__global__ void k_fill(){
  int e = blockIdx.x*blockDim.x + threadIdx.x;
  if (e >= MM) return;
  int d = g_dst[e];
  int p = atomicAdd(&g_cursor[d], 1);
  g_csr[p] = make_int2(g_src[e], __float_as_int(g_alpha[e]));
}

__global__ void k_h(const float* __restrict__ x, const float* __restrict__ u,
                    const float* __restrict__ Wi, const float* __restrict__ bi){
  __shared__ float sW[H*NIF], su[11], sb[H];
  int t = threadIdx.x;
  for (int i = t; i < H*NIF; i += blockDim.x) sW[i] = Wi[i];
  if (t < 11) su[t] = u[t];
  if (t < H) sb[t] = bi[t];
  __syncthreads();
  int idx = blockIdx.x*blockDim.x + t;
  if (idx >= NN*H) return;
  int node = idx >> 6, j = idx & 63;
  const float* w = &sW[j*NIF];
  const float* xr = &x[node*12];
  float acc = sb[j];
  #pragma unroll
  for (int k = 0; k < 12; k++) acc = fmaf(xr[k], w[k], acc);
  #pragma unroll
  for (int k = 0; k < 11; k++) acc = fmaf(su[k], w[12+k], acc);
  g_hA[idx] = tanhf(acc);
}

__global__ void k_hm(const float* __restrict__ hin,
                     const float* __restrict__ W, const float* __restrict__ b){
  __shared__ float sWt[H*H], sb[H];
  int t = threadIdx.x;
  for (int i = t; i < H*H; i += blockDim.x){ int j = i >> 6, k = i & 63; sWt[k*H + j] = W[i]; }
  if (t < H) sb[t] = b[t];
  __syncthreads();
  int lane = t & 31;
  int wg = (blockIdx.x*blockDim.x + t) >> 5;
  int nw = (gridDim.x*blockDim.x) >> 5;
  for (int n = wg; n < NN; n += nw){
    float v0 = hin[(n<<6) + lane], v1 = hin[(n<<6) + 32 + lane];
    float a0 = sb[lane], a1 = sb[32 + lane];
    #pragma unroll
    for (int k = 0; k < 32; k++){
      float hk = __shfl_sync(0xffffffffu, v0, k);
      a0 = fmaf(hk, sWt[k*H + lane], a0);
      a1 = fmaf(hk, sWt[k*H + 32 + lane], a1);
    }
    #pragma unroll
    for (int k = 0; k < 32; k++){
      float hk = __shfl_sync(0xffffffffu, v1, k);
      a0 = fmaf(hk, sWt[(32+k)*H + lane], a0);
      a1 = fmaf(hk, sWt[(32+k)*H + 32 + lane], a1);
    }
    g_hm[(n<<6) + lane]      = fmaxf(a0, 0.f);
    g_hm[(n<<6) + 32 + lane] = fmaxf(a1, 0.f);
  }
}

__global__ void k_agg(){
  int w = (blockIdx.x*blockDim.x + threadIdx.x) >> 5;
  int lane = threadIdx.x & 31;
  if (w >= NN) return;
  int beg = g_rowptr[w], end = g_rowptr[w+1];
  float a0 = 0.f, a1 = 0.f;
  int i = beg;
  for (; i + 1 < end; i += 2){
    int2 e0 = g_csr[i], e1 = g_csr[i+1];
    float al0 = __int_as_float(e0.y), al1 = __int_as_float(e1.y);
    const float* p0 = &g_hm[(size_t)e0.x << 6];
    const float* p1 = &g_hm[(size_t)e1.x << 6];
    a0 = fmaf(al0, p0[lane], a0); a1 = fmaf(al0, p0[lane+32], a1);
    a0 = fmaf(al1, p1[lane], a0); a1 = fmaf(al1, p1[lane+32], a1);
  }
  if (i < end){
    int2 e0 = g_csr[i];
    float al0 = __int_as_float(e0.y);
    const float* p0 = &g_hm[(size_t)e0.x << 6];
    a0 = fmaf(al0, p0[lane], a0); a1 = fmaf(al0, p0[lane+32], a1);
  }
  float inv = 1.f / fmaxf((float)(end - beg), 1.f);
  g_agg[(w<<6) + lane]      = a0 * inv;
  g_agg[(w<<6) + 32 + lane] = a1 * inv;
}

#define GNB 8
__global__ void __launch_bounds__(256) k_gru(
    const float* __restrict__ hin, float* __restrict__ hout,
    const float* __restrict__ Wih, const float* __restrict__ bih,
    const float* __restrict__ Whh, const float* __restrict__ bhh){
  extern __shared__ float smem[];
  float* sWi = smem;            // [64][192] transposed
  float* sWh = smem + 64*192;
  __shared__ float sbi[192], sbh[192];
  int t = threadIdx.x;
  for (int i = t; i < 192*64; i += blockDim.x){
    int j = i / 64, k = i % 64;
    sWi[k*192 + j] = Wih[i];
    sWh[k*192 + j] = Whh[i];
  }
  for (int i = t; i < 192; i += blockDim.x){ sbi[i] = bih[i]; sbh[i] = bhh[i]; }
  __syncthreads();
  int j = t & 63, q = t >> 6, lane = t & 31;
  int c = blockIdx.x;
  int nbase = c*32 + q*GNB;
  float ra0[GNB], ra1[GNB], rh0[GNB], rh1[GNB];
  #pragma unroll
  for (int i = 0; i < GNB; i++){
    int n = min(nbase + i, NN - 1);
    ra0[i] = g_agg[(n<<6) + lane];  ra1[i] = g_agg[(n<<6) + 32 + lane];
    rh0[i] = hin[(n<<6) + lane];    rh1[i] = hin[(n<<6) + 32 + lane];
  }
  float aR[GNB], aZ[GNB], aN[GNB], hR[GNB], hZ[GNB], hN[GNB];
  #pragma unroll
  for (int i = 0; i < GNB; i++){ aR[i]=aZ[i]=aN[i]=hR[i]=hZ[i]=hN[i]=0.f; }
  #pragma unroll 4
  for (int k = 0; k < 32; k++){
    float wir = sWi[k*192 + j], wiz = sWi[k*192 + 64 + j], win = sWi[k*192 + 128 + j];
    float whr = sWh[k*192 + j], whz = sWh[k*192 + 64 + j], whn = sWh[k*192 + 128 + j];
    #pragma unroll
    for (int i = 0; i < GNB; i++){
      float av = __shfl_sync(0xffffffffu, ra0[i], k);
      float hv = __shfl_sync(0xffffffffu, rh0[i], k);
      aR[i] = fmaf(av, wir, aR[i]); aZ[i] = fmaf(av, wiz, aZ[i]); aN[i] = fmaf(av, win, aN[i]);
      hR[i] = fmaf(hv, whr, hR[i]); hZ[i] = fmaf(hv, whz, hZ[i]); hN[i] = fmaf(hv, whn, hN[i]);
    }
  }
  #pragma unroll 4
  for (int k = 32; k < 64; k++){
    float wir = sWi[k*192 + j], wiz = sWi[k*192 + 64 + j], win = sWi[k*192 + 128 + j];
    float whr = sWh[k*192 + j], whz = sWh[k*192 + 64 + j], whn = sWh[k*192 + 128 + j];
    #pragma unroll
    for (int i = 0; i < GNB; i++){
      float av = __shfl_sync(0xffffffffu, ra1[i], k - 32);
      float hv = __shfl_sync(0xffffffffu, rh1[i], k - 32);
      aR[i] = fmaf(av, wir, aR[i]); aZ[i] = fmaf(av, wiz, aZ[i]); aN[i] = fmaf(av, win, aN[i]);
      hR[i] = fmaf(hv, whr, hR[i]); hZ[i] = fmaf(hv, whz, hZ[i]); hN[i] = fmaf(hv, whn, hN[i]);
    }
  }
  float bir = sbi[j], biz = sbi[64+j], bin_ = sbi[128+j];
  float bhr = sbh[j], bhz = sbh[64+j], bhn  = sbh[128+j];
  #pragma unroll
  for (int i = 0; i < GNB; i++){
    int n = nbase + i;
    if (n < NN){
      float r  = sigf(aR[i] + bir + hR[i] + bhr);
      float z  = sigf(aZ[i] + biz + hZ[i] + bhz);
      float ng = tanhf(aN[i] + bin_ + r*(hN[i] + bhn));
      float ho = hin[(n<<6) + j];
      hout[(n<<6) + j] = (1.f - z)*ng + z*ho;
    }
  }
}

__global__ void k_AB(const float* __restrict__ hin,
                     const float* __restrict__ W1, const float* __restrict__ b1){
  __shared__ float sAt[H*H], sBt[H*H], sb[H];
  int t = threadIdx.x;
  for (int i = t; i < H*H; i += blockDim.x){
    int j = i >> 6, k = i & 63;
    sAt[k*H + j] = W1[j*133 + k];
    sBt[k*H + j] = W1[j*133 + 64 + k];
  }
  if (t < H) sb[t] = b1[t];
  __syncthreads();
  int lane = t & 31;
  int wg = (blockIdx.x*blockDim.x + t) >> 5;
  int nw = (gridDim.x*blockDim.x) >> 5;
  for (int n = wg; n < NN; n += nw){
    float v0 = hin[(n<<6) + lane], v1 = hin[(n<<6) + 32 + lane];
    float a0 = sb[lane], a1 = sb[32+lane], b0 = 0.f, b1v = 0.f;
    #pragma unroll
    for (int k = 0; k < 32; k++){
      float hk = __shfl_sync(0xffffffffu, v0, k);
      a0 = fmaf(hk, sAt[k*H + lane], a0);      a1 = fmaf(hk, sAt[k*H + 32 + lane], a1);
      b0 = fmaf(hk, sBt[k*H + lane], b0);      b1v = fmaf(hk, sBt[k*H + 32 + lane], b1v);
    }
    #pragma unroll
    for (int k = 0; k < 32; k++){
      float hk = __shfl_sync(0xffffffffu, v1, k);
      a0 = fmaf(hk, sAt[(32+k)*H + lane], a0); a1 = fmaf(hk, sAt[(32+k)*H + 32 + lane], a1);
      b0 = fmaf(hk, sBt[(32+k)*H + lane], b0); b1v = fmaf(hk, sBt[(32+k)*H + 32 + lane], b1v);
    }
    g_Ad[(n<<6) + lane]      = a0;  g_Ad[(n<<6) + 32 + lane] = a1;
    g_Bd[(n<<6) + lane]      = b0;  g_Bd[(n<<6) + 32 + lane] = b1v;
  }
}

__global__ void __launch_bounds__(128) k_dec(
    const float* __restrict__ ea, float* __restrict__ out,
    const float* __restrict__ W1, const float* __restrict__ W2,
    const float* __restrict__ b2, const float* __restrict__ W3,
    const float* __restrict__ b3){
  __shared__ float4 sW1e4[5*16];   // [k][j/4], W1 edge part transposed
  __shared__ float4 sW2t4[64*8];   // [k][j/4], W2 transposed
  __shared__ float4 sW3t4[32];     // [k], W3 transposed
  __shared__ float sb2[32], sb3[4];
  int t = threadIdx.x;
  {
    float* p = (float*)sW1e4;
    for (int i = t; i < 5*64; i += blockDim.x){ int k = i >> 6, j = i & 63; p[k*64 + j] = W1[j*133 + 128 + k]; }
    float* p2 = (float*)sW2t4;
    for (int i = t; i < 64*32; i += blockDim.x){ int j = i >> 6, k = i & 63; p2[k*32 + j] = W2[j*64 + k]; }
    float* p3 = (float*)sW3t4;
    for (int i = t; i < 32*4; i += blockDim.x){ int j = i >> 5, k = i & 31; p3[k*4 + j] = W3[j*32 + k]; }
    if (t < 32) sb2[t] = b2[t];
    if (t < 4)  sb3[t] = b3[t];
  }
  __syncthreads();
  int e = blockIdx.x*blockDim.x + t;
  if (e >= MM) return;
  int s = g_src[e], d = g_dst[e];
  const float4* pA = (const float4*)&g_Ad[(size_t)s << 6];
  const float4* pB = (const float4*)&g_Bd[(size_t)d << 6];
  float s1[64];
  #pragma unroll
  for (int q = 0; q < 16; q++){
    float4 a = __ldg(&pA[q]); float4 b = __ldg(&pB[q]);
    s1[4*q] = a.x + b.x; s1[4*q+1] = a.y + b.y; s1[4*q+2] = a.z + b.z; s1[4*q+3] = a.w + b.w;
  }
  float eav[5];
  #pragma unroll
  for (int k = 0; k < 5; k++) eav[k] = ea[e*5 + k];
  #pragma unroll
  for (int k = 0; k < 5; k++){
    float v = eav[k];
    #pragma unroll
    for (int q = 0; q < 16; q++){
      float4 w = sW1e4[k*16 + q];
      s1[4*q]   = fmaf(v, w.x, s1[4*q]);
      s1[4*q+1] = fmaf(v, w.y, s1[4*q+1]);
      s1[4*q+2] = fmaf(v, w.z, s1[4*q+2]);
      s1[4*q+3] = fmaf(v, w.w, s1[4*q+3]);
    }
  }
  #pragma unroll
  for (int j = 0; j < 64; j++) s1[j] = fmaxf(s1[j], 0.f);
  float a2[32];
  #pragma unroll
  for (int j = 0; j < 32; j++) a2[j] = sb2[j];
  #pragma unroll
  for (int k = 0; k < 64; k++){
    float v = s1[k];
    #pragma unroll
    for (int q = 0; q < 8; q++){
      float4 w = sW2t4[k*8 + q];
      a2[4*q]   = fmaf(v, w.x, a2[4*q]);
      a2[4*q+1] = fmaf(v, w.y, a2[4*q+1]);
      a2[4*q+2] = fmaf(v, w.z, a2[4*q+2]);
      a2[4*q+3] = fmaf(v, w.w, a2[4*q+3]);
    }
  }
  #pragma unroll
  for (int j = 0; j < 32; j++) a2[j] = fmaxf(a2[j], 0.f);
  float o0 = sb3[0], o1 = sb3[1], o2 = sb3[2], o3 = sb3[3];
  #pragma unroll
  for (int k = 0; k < 32; k++){
    float4 w = sW3t4[k]; float v = a2[k];
    o0 = fmaf(v, w.x, o0); o1 = fmaf(v, w.y, o1); o2 = fmaf(v, w.z, o2); o3 = fmaf(v, w.w, o3);
  }
  ((float4*)out)[e] = make_float4(o0, o1, o2, o3);
}

extern "C" void kernel_launch(void* const* d_in, const int* in_sizes, int n_in,
                              void* d_out, int out_size){
  (void)in_sizes; (void)n_in; (void)out_size;
  const float* x    = (const float*)d_in[0];
  const void*  ei   = d_in[1];
  const float* ea   = (const float*)d_in[2];
  const float* u    = (const float*)d_in[3];
  const float* Win  = (const float*)d_in[4];
  const float* bin  = (const float*)d_in[5];
  const float* eW1  = (const float*)d_in[6];
  const float* eb1  = (const float*)d_in[7];
  const float* eW2  = (const float*)d_in[8];
  const float* eb2  = (const float*)d_in[9];
  const float* msW  = (const float*)d_in[10];
  const float* msb  = (const float*)d_in[11];
  const float* Wih  = (const float*)d_in[12];
  const float* bih  = (const float*)d_in[13];
  const float* Whh  = (const float*)d_in[14];
  const float* bhh  = (const float*)d_in[15];
  const float* dW1  = (const float*)d_in[16];
  const float* db1  = (const float*)d_in[17];
  const float* dW2  = (const float*)d_in[18];
  const float* db2  = (const float*)d_in[19];
  const float* dW3  = (const float*)d_in[20];
  const float* db3  = (const float*)d_in[21];
  float* out = (float*)d_out;

  static int attr_done = 0;
  if (!attr_done){
    cudaFuncSetAttribute(k_gru, cudaFuncAttributeMaxDynamicSharedMemorySize, 2*64*192*4);
    attr_done = 1;
  }

  k_detect<<<1, 256>>>((const int*)ei);
  k_zero<<<(NN + 255)/256, 256>>>();
  k_prep<<<(MM + 255)/256, 256>>>(ei, ea, u, eW1, eb1, eW2, eb2);
  k_scan<<<1, 1024>>>();
  k_fill<<<(MM + 255)/256, 256>>>();
  k_h<<<(NN*H + 255)/256, 256>>>(x, u, Win, bin);

  const int GRID_W = 1184;   // warp-per-node persistent kernels
  const int GRID_AGG = (NN*32 + 255)/256;
  const int GRID_GRU = (NN + 31)/32;
  float* hcur = g_hA;  // device symbol addresses resolved below via kernels' direct use
  // ping-pong via explicit launches (symbols used directly inside kernels)
  // step 1: hA -> hB ; step 2: hB -> hA ; step 3: hA -> hB
  {
    float *hA_p = nullptr, *hB_p = nullptr;
    cudaGetSymbolAddress((void**)&hA_p, g_hA);
    cudaGetSymbolAddress((void**)&hB_p, g_hB);
    k_hm<<<GRID_W, 256>>>(hA_p, msW, msb);
    k_agg<<<GRID_AGG, 256>>>();
    k_gru<<<GRID_GRU, 256, 2*64*192*4>>>(hA_p, hB_p, Wih, bih, Whh, bhh);

    k_hm<<<GRID_W, 256>>>(hB_p, msW, msb);
    k_agg<<<GRID_AGG, 256>>>();
    k_gru<<<GRID_GRU, 256, 2*64*192*4>>>(hB_p, hA_p, Wih, bih, Whh, bhh);

    k_hm<<<GRID_W, 256>>>(hA_p, msW, msb);
    k_agg<<<GRID_AGG, 256>>>();
    k_gru<<<GRID_GRU, 256, 2*64*192*4>>>(hA_p, hB_p, Wih, bih, Whh, bhh);

    k_AB<<<GRID_W, 256>>>(hB_p, dW1, db1);
  }
  (void)hcur;
  k_dec<<<(MM + 127)/128, 128>>>(ea, out, dW1, dW2, db2, dW3, db3);
}

// round 3
// speedup vs baseline: 1.4534x; 1.4534x over previous
#include <cuda_runtime.h>
#include <math.h>

#define NN 50000
#define MM 1250000
#define H  64
#define EF 16
#define NIF 23
#define EWH 32

__device__ float g_hA[NN*H];
__device__ float g_hB[NN*H];
__device__ float g_hm[NN*H];
__device__ float g_agg[NN*H];
__device__ float g_Ad[NN*H];
__device__ float g_Bd[NN*H];
__device__ float g_alpha[MM];
__device__ int   g_src[MM];
__device__ int   g_dst[MM];
__device__ int2  g_csr[MM];
__device__ int   g_cnt[NN];
__device__ int   g_rowptr[NN+1];
__device__ int   g_cursor[NN];
__device__ int   g_is64;

__device__ __forceinline__ float sigf(float x){ return 1.f/(1.f+__expf(-x)); }

__global__ void k_zero(){
  int i = blockIdx.x*blockDim.x + threadIdx.x;
  if (i < NN) g_cnt[i] = 0;
}

__global__ void k_detect(const int* __restrict__ ei){
  __shared__ int nz;
  if (threadIdx.x == 0) nz = 0;
  __syncthreads();
  int c = 0;
  for (int i = threadIdx.x; i < 4096; i += blockDim.x) c += (ei[2*i+1] != 0);
  if (c) atomicAdd(&nz, 1);
  __syncthreads();
  if (threadIdx.x == 0) g_is64 = (nz == 0);
}

__global__ void k_prep(const void* __restrict__ ei, const float* __restrict__ ea,
                       const float* __restrict__ u,
                       const float* __restrict__ W1, const float* __restrict__ b1,
                       const float* __restrict__ W2, const float* __restrict__ b2){
  __shared__ float sW[EWH*EF], sb1[EWH], sW2[EWH], su[11], sb2;
  int t = threadIdx.x;
  for (int i = t; i < EWH*EF; i += blockDim.x) sW[i] = W1[i];
  if (t < EWH){ sb1[t] = b1[t]; sW2[t] = W2[t]; }
  if (t < 11) su[t] = u[t];
  if (t == 0) sb2 = b2[0];
  __syncthreads();
  int e = blockIdx.x*blockDim.x + t;
  if (e >= MM) return;
  int s, d;
  if (g_is64){
    const long long* p = (const long long*)ei;
    s = (int)p[e]; d = (int)p[MM + e];
  } else {
    const int* p = (const int*)ei;
    s = p[e]; d = p[MM + e];
  }
  g_src[e] = s; g_dst[e] = d;
  atomicAdd(&g_cnt[d], 1);
  float f[EF];
  #pragma unroll
  for (int k = 0; k < 5; k++) f[k] = ea[e*5 + k];
  #pragma unroll
  for (int k = 0; k < 11; k++) f[5+k] = su[k];
  float acc = sb2;
  #pragma unroll
  for (int i = 0; i < EWH; i++){
    float a = sb1[i];
    #pragma unroll
    for (int k = 0; k < EF; k++) a = fmaf(f[k], sW[i*EF + k], a);
    acc = fmaf(fmaxf(a, 0.f), sW2[i], acc);
  }
  g_alpha[e] = sigf(acc);
}

// fast single-block scan: 1024 threads, 49 elems each, shuffle block scan
__global__ void k_scan(){
  __shared__ int wsum[32];
  const int PER = 49;   // 1024*49 = 50176 >= NN
  int t = threadIdx.x;
  int base = t * PER;
  int sum = 0;
  for (int k = 0; k < PER; k++){ int i = base + k; if (i < NN) sum += g_cnt[i]; }
  int lane = t & 31, wid = t >> 5;
  int v = sum;
  #pragma unroll
  for (int o = 1; o < 32; o <<= 1){ int u = __shfl_up_sync(~0u, v, o); if (lane >= o) v += u; }
  if (lane == 31) wsum[wid] = v;
  __syncthreads();
  if (wid == 0){
    int w = wsum[lane];
    #pragma unroll
    for (int o = 1; o < 32; o <<= 1){ int u = __shfl_up_sync(~0u, w, o); if (lane >= o) w += u; }
    wsum[lane] = w;
  }
  __syncthreads();
  int excl = v - sum + (wid ? wsum[wid-1] : 0);
  if (t == 0) g_rowptr[0] = 0;
  int run = excl;
  for (int k = 0; k < PER; k++){
    int i = base + k;
    if (i < NN){ int c = g_cnt[i]; g_cursor[i] = run; run += c; g_rowptr[i+1] = run; }
  }
}

__global__ void k_fill(){
  int e = blockIdx.x*blockDim.x + threadIdx.x;
  if (e >= MM) return;
  int d = g_dst[e];
  int p = atomicAdd(&g_cursor[d], 1);
  g_csr[p] = make_int2(g_src[e], __float_as_int(g_alpha[e]));
}

__global__ void k_h(const float* __restrict__ x, const float* __restrict__ u,
                    const float* __restrict__ Wi, const float* __restrict__ bi){
  __shared__ float sW[H*NIF], su[11], sb[H];
  int t = threadIdx.x;
  for (int i = t; i < H*NIF; i += blockDim.x) sW[i] = Wi[i];
  if (t < 11) su[t] = u[t];
  if (t < H) sb[t] = bi[t];
  __syncthreads();
  int idx = blockIdx.x*blockDim.x + t;
  if (idx >= NN*H) return;
  int node = idx >> 6, j = idx & 63;
  const float* w = &sW[j*NIF];
  const float* xr = &x[node*12];
  float acc = sb[j];
  #pragma unroll
  for (int k = 0; k < 12; k++) acc = fmaf(xr[k], w[k], acc);
  #pragma unroll
  for (int k = 0; k < 11; k++) acc = fmaf(su[k], w[12+k], acc);
  g_hA[idx] = tanhf(acc);
}

// hm = relu(h@W.T + b), warp per node; transposed weights padded to stride 65
__global__ void k_hm(const float* __restrict__ hin,
                     const float* __restrict__ W, const float* __restrict__ b){
  __shared__ float sWt[H*65], sb[H];
  int t = threadIdx.x;
  for (int i = t; i < H*H; i += blockDim.x){ int j = i >> 6, k = i & 63; sWt[k*65 + j] = W[i]; }
  if (t < H) sb[t] = b[t];
  __syncthreads();
  int lane = t & 31;
  int wg = (blockIdx.x*blockDim.x + t) >> 5;
  int nw = (gridDim.x*blockDim.x) >> 5;
  for (int n = wg; n < NN; n += nw){
    float v0 = hin[(n<<6) + lane], v1 = hin[(n<<6) + 32 + lane];
    float a0 = sb[lane], a1 = sb[32 + lane];
    #pragma unroll
    for (int k = 0; k < 32; k++){
      float hk = __shfl_sync(0xffffffffu, v0, k);
      a0 = fmaf(hk, sWt[k*65 + lane], a0);
      a1 = fmaf(hk, sWt[k*65 + 32 + lane], a1);
    }
    #pragma unroll
    for (int k = 0; k < 32; k++){
      float hk = __shfl_sync(0xffffffffu, v1, k);
      a0 = fmaf(hk, sWt[(32+k)*65 + lane], a0);
      a1 = fmaf(hk, sWt[(32+k)*65 + 32 + lane], a1);
    }
    g_hm[(n<<6) + lane]      = fmaxf(a0, 0.f);
    g_hm[(n<<6) + 32 + lane] = fmaxf(a1, 0.f);
  }
}

__global__ void k_agg(){
  int w = (blockIdx.x*blockDim.x + threadIdx.x) >> 5;
  int lane = threadIdx.x & 31;
  if (w >= NN) return;
  int beg = g_rowptr[w], end = g_rowptr[w+1];
  float a0 = 0.f, a1 = 0.f;
  int i = beg;
  for (; i + 1 < end; i += 2){
    int2 e0 = g_csr[i], e1 = g_csr[i+1];
    float al0 = __int_as_float(e0.y), al1 = __int_as_float(e1.y);
    const float* p0 = &g_hm[(size_t)e0.x << 6];
    const float* p1 = &g_hm[(size_t)e1.x << 6];
    a0 = fmaf(al0, p0[lane], a0); a1 = fmaf(al0, p0[lane+32], a1);
    a0 = fmaf(al1, p1[lane], a0); a1 = fmaf(al1, p1[lane+32], a1);
  }
  if (i < end){
    int2 e0 = g_csr[i];
    float al0 = __int_as_float(e0.y);
    const float* p0 = &g_hm[(size_t)e0.x << 6];
    a0 = fmaf(al0, p0[lane], a0); a1 = fmaf(al0, p0[lane+32], a1);
  }
  float inv = 1.f / fmaxf((float)(end - beg), 1.f);
  g_agg[(w<<6) + lane]      = a0 * inv;
  g_agg[(w<<6) + 32 + lane] = a1 * inv;
}

// GRU: persistent blocks, padded transposed weights (stride 193, conflict-free)
#define GNB 8
#define GRU_STRIDE 193
#define GRU_SMEM (2*64*GRU_STRIDE*4)
__global__ void __launch_bounds__(256) k_gru(
    const float* __restrict__ hin, float* __restrict__ hout,
    const float* __restrict__ Wih, const float* __restrict__ bih,
    const float* __restrict__ Whh, const float* __restrict__ bhh){
  extern __shared__ float smem[];
  float* sWi = smem;                 // [64][193] transposed, padded
  float* sWh = smem + 64*GRU_STRIDE;
  __shared__ float sbi[192], sbh[192];
  int t = threadIdx.x;
  for (int i = t; i < 192*64; i += blockDim.x){
    int j = i / 64, k = i % 64;
    sWi[k*GRU_STRIDE + j] = Wih[i];
    sWh[k*GRU_STRIDE + j] = Whh[i];
  }
  for (int i = t; i < 192; i += blockDim.x){ sbi[i] = bih[i]; sbh[i] = bhh[i]; }
  __syncthreads();
  int j = t & 63, q = t >> 6, lane = t & 31;
  int nchunks = (NN + 31) / 32;
  for (int c = blockIdx.x; c < nchunks; c += gridDim.x){
    int nbase = c*32 + q*GNB;
    float ra0[GNB], ra1[GNB], rh0[GNB], rh1[GNB];
    #pragma unroll
    for (int i = 0; i < GNB; i++){
      int n = min(nbase + i, NN - 1);
      ra0[i] = g_agg[(n<<6) + lane];  ra1[i] = g_agg[(n<<6) + 32 + lane];
      rh0[i] = hin[(n<<6) + lane];    rh1[i] = hin[(n<<6) + 32 + lane];
    }
    float aR[GNB], aZ[GNB], aN[GNB], hR[GNB], hZ[GNB], hN[GNB];
    #pragma unroll
    for (int i = 0; i < GNB; i++){ aR[i]=aZ[i]=aN[i]=hR[i]=hZ[i]=hN[i]=0.f; }
    #pragma unroll 4
    for (int k = 0; k < 32; k++){
      float wir = sWi[k*GRU_STRIDE + j], wiz = sWi[k*GRU_STRIDE + 64 + j], win = sWi[k*GRU_STRIDE + 128 + j];
      float whr = sWh[k*GRU_STRIDE + j], whz = sWh[k*GRU_STRIDE + 64 + j], whn = sWh[k*GRU_STRIDE + 128 + j];
      #pragma unroll
      for (int i = 0; i < GNB; i++){
        float av = __shfl_sync(0xffffffffu, ra0[i], k);
        float hv = __shfl_sync(0xffffffffu, rh0[i], k);
        aR[i] = fmaf(av, wir, aR[i]); aZ[i] = fmaf(av, wiz, aZ[i]); aN[i] = fmaf(av, win, aN[i]);
        hR[i] = fmaf(hv, whr, hR[i]); hZ[i] = fmaf(hv, whz, hZ[i]); hN[i] = fmaf(hv, whn, hN[i]);
      }
    }
    #pragma unroll 4
    for (int k = 32; k < 64; k++){
      float wir = sWi[k*GRU_STRIDE + j], wiz = sWi[k*GRU_STRIDE + 64 + j], win = sWi[k*GRU_STRIDE + 128 + j];
      float whr = sWh[k*GRU_STRIDE + j], whz = sWh[k*GRU_STRIDE + 64 + j], whn = sWh[k*GRU_STRIDE + 128 + j];
      #pragma unroll
      for (int i = 0; i < GNB; i++){
        float av = __shfl_sync(0xffffffffu, ra1[i], k - 32);
        float hv = __shfl_sync(0xffffffffu, rh1[i], k - 32);
        aR[i] = fmaf(av, wir, aR[i]); aZ[i] = fmaf(av, wiz, aZ[i]); aN[i] = fmaf(av, win, aN[i]);
        hR[i] = fmaf(hv, whr, hR[i]); hZ[i] = fmaf(hv, whz, hZ[i]); hN[i] = fmaf(hv, whn, hN[i]);
      }
    }
    float bir = sbi[j], biz = sbi[64+j], bin_ = sbi[128+j];
    float bhr = sbh[j], bhz = sbh[64+j], bhn  = sbh[128+j];
    #pragma unroll
    for (int i = 0; i < GNB; i++){
      int n = nbase + i;
      if (n < NN){
        float r  = sigf(aR[i] + bir + hR[i] + bhr);
        float z  = sigf(aZ[i] + biz + hZ[i] + bhz);
        float ng = tanhf(aN[i] + bin_ + r*(hN[i] + bhn));
        float ho = hin[(n<<6) + j];
        hout[(n<<6) + j] = (1.f - z)*ng + z*ho;
      }
    }
  }
}

// A = h@W1a.T + b1, B = h@W1b.T ; padded transposed weights stride 65
__global__ void k_AB(const float* __restrict__ hin,
                     const float* __restrict__ W1, const float* __restrict__ b1){
  __shared__ float sAt[H*65], sBt[H*65], sb[H];
  int t = threadIdx.x;
  for (int i = t; i < H*H; i += blockDim.x){
    int j = i >> 6, k = i & 63;
    sAt[k*65 + j] = W1[j*133 + k];
    sBt[k*65 + j] = W1[j*133 + 64 + k];
  }
  if (t < H) sb[t] = b1[t];
  __syncthreads();
  int lane = t & 31;
  int wg = (blockIdx.x*blockDim.x + t) >> 5;
  int nw = (gridDim.x*blockDim.x) >> 5;
  for (int n = wg; n < NN; n += nw){
    float v0 = hin[(n<<6) + lane], v1 = hin[(n<<6) + 32 + lane];
    float a0 = sb[lane], a1 = sb[32+lane], b0 = 0.f, b1v = 0.f;
    #pragma unroll
    for (int k = 0; k < 32; k++){
      float hk = __shfl_sync(0xffffffffu, v0, k);
      a0 = fmaf(hk, sAt[k*65 + lane], a0);      a1 = fmaf(hk, sAt[k*65 + 32 + lane], a1);
      b0 = fmaf(hk, sBt[k*65 + lane], b0);      b1v = fmaf(hk, sBt[k*65 + 32 + lane], b1v);
    }
    #pragma unroll
    for (int k = 0; k < 32; k++){
      float hk = __shfl_sync(0xffffffffu, v1, k);
      a0 = fmaf(hk, sAt[(32+k)*65 + lane], a0); a1 = fmaf(hk, sAt[(32+k)*65 + 32 + lane], a1);
      b0 = fmaf(hk, sBt[(32+k)*65 + lane], b0); b1v = fmaf(hk, sBt[(32+k)*65 + 32 + lane], b1v);
    }
    g_Ad[(n<<6) + lane]      = a0;  g_Ad[(n<<6) + 32 + lane] = a1;
    g_Bd[(n<<6) + lane]      = b0;  g_Bd[(n<<6) + 32 + lane] = b1v;
  }
}

// decoder: dot-product form, weights staged in native row-major layout,
// read as uniform-broadcast float4 LDS (conflict-free both directions)
__global__ void __launch_bounds__(256) k_dec(
    const float* __restrict__ ea, float* __restrict__ out,
    const float* __restrict__ W1, const float* __restrict__ W2,
    const float* __restrict__ b2, const float* __restrict__ W3,
    const float* __restrict__ b3){
  __shared__ float  sW1e[64*5];    // [j][k] edge slice of W1
  __shared__ float4 sW2[32*16];    // [j][k/4] row-major W2
  __shared__ float4 sW3[4*8];      // [j][k/4] row-major W3
  __shared__ float sb2[32], sb3[4];
  int t = threadIdx.x;
  for (int i = t; i < 64*5; i += blockDim.x){ int j = i/5, k = i%5; sW1e[i] = W1[j*133 + 128 + k]; }
  {
    float* p2 = (float*)sW2;
    for (int i = t; i < 64*32; i += blockDim.x) p2[i] = W2[i];
    float* p3 = (float*)sW3;
    for (int i = t; i < 32*4; i += blockDim.x) p3[i] = W3[i];
  }
  if (t < 32) sb2[t] = b2[t];
  if (t < 4)  sb3[t] = b3[t];
  __syncthreads();
  int e = blockIdx.x*blockDim.x + t;
  if (e >= MM) return;
  int s = g_src[e], d = g_dst[e];
  const float4* pA = (const float4*)&g_Ad[(size_t)s << 6];
  const float4* pB = (const float4*)&g_Bd[(size_t)d << 6];
  float s1[64];
  #pragma unroll
  for (int q = 0; q < 16; q++){
    float4 a = __ldg(&pA[q]); float4 b = __ldg(&pB[q]);
    s1[4*q] = a.x + b.x; s1[4*q+1] = a.y + b.y; s1[4*q+2] = a.z + b.z; s1[4*q+3] = a.w + b.w;
  }
  float eav[5];
  #pragma unroll
  for (int k = 0; k < 5; k++) eav[k] = ea[e*5 + k];
  #pragma unroll
  for (int j = 0; j < 64; j++){
    float acc = s1[j];
    #pragma unroll
    for (int k = 0; k < 5; k++) acc = fmaf(eav[k], sW1e[j*5 + k], acc);
    s1[j] = fmaxf(acc, 0.f);
  }
  float a2[32];
  #pragma unroll
  for (int j = 0; j < 32; j++){
    float acc = sb2[j];
    #pragma unroll
    for (int q = 0; q < 16; q++){
      float4 w = sW2[j*16 + q];
      acc = fmaf(s1[4*q],   w.x, acc);
      acc = fmaf(s1[4*q+1], w.y, acc);
      acc = fmaf(s1[4*q+2], w.z, acc);
      acc = fmaf(s1[4*q+3], w.w, acc);
    }
    a2[j] = fmaxf(acc, 0.f);
  }
  float o[4];
  #pragma unroll
  for (int j = 0; j < 4; j++){
    float acc = sb3[j];
    #pragma unroll
    for (int q = 0; q < 8; q++){
      float4 w = sW3[j*8 + q];
      acc = fmaf(a2[4*q],   w.x, acc);
      acc = fmaf(a2[4*q+1], w.y, acc);
      acc = fmaf(a2[4*q+2], w.z, acc);
      acc = fmaf(a2[4*q+3], w.w, acc);
    }
    o[j] = acc;
  }
  ((float4*)out)[e] = make_float4(o[0], o[1], o[2], o[3]);
}

extern "C" void kernel_launch(void* const* d_in, const int* in_sizes, int n_in,
                              void* d_out, int out_size){
  (void)in_sizes; (void)n_in; (void)out_size;
  const float* x    = (const float*)d_in[0];
  const void*  ei   = d_in[1];
  const float* ea   = (const float*)d_in[2];
  const float* u    = (const float*)d_in[3];
  const float* Win  = (const float*)d_in[4];
  const float* bin  = (const float*)d_in[5];
  const float* eW1  = (const float*)d_in[6];
  const float* eb1  = (const float*)d_in[7];
  const float* eW2  = (const float*)d_in[8];
  const float* eb2  = (const float*)d_in[9];
  const float* msW  = (const float*)d_in[10];
  const float* msb  = (const float*)d_in[11];
  const float* Wih  = (const float*)d_in[12];
  const float* bih  = (const float*)d_in[13];
  const float* Whh  = (const float*)d_in[14];
  const float* bhh  = (const float*)d_in[15];
  const float* dW1  = (const float*)d_in[16];
  const float* db1  = (const float*)d_in[17];
  const float* dW2  = (const float*)d_in[18];
  const float* db2  = (const float*)d_in[19];
  const float* dW3  = (const float*)d_in[20];
  const float* db3  = (const float*)d_in[21];
  float* out = (float*)d_out;

  static int attr_done = 0;
  if (!attr_done){
    cudaFuncSetAttribute(k_gru, cudaFuncAttributeMaxDynamicSharedMemorySize, GRU_SMEM);
    attr_done = 1;
  }

  k_detect<<<1, 256>>>((const int*)ei);
  k_zero<<<(NN + 255)/256, 256>>>();
  k_prep<<<(MM + 255)/256, 256>>>(ei, ea, u, eW1, eb1, eW2, eb2);
  k_scan<<<1, 1024>>>();
  k_fill<<<(MM + 255)/256, 256>>>();
  k_h<<<(NN*H + 255)/256, 256>>>(x, u, Win, bin);

  const int GRID_W   = 1184;
  const int GRID_AGG = (NN*32 + 255)/256;
  const int GRID_GRU = 296;      // persistent; chunk loop inside

  float *hA_p = nullptr, *hB_p = nullptr;
  cudaGetSymbolAddress((void**)&hA_p, g_hA);
  cudaGetSymbolAddress((void**)&hB_p, g_hB);

  k_hm<<<GRID_W, 256>>>(hA_p, msW, msb);
  k_agg<<<GRID_AGG, 256>>>();
  k_gru<<<GRID_GRU, 256, GRU_SMEM>>>(hA_p, hB_p, Wih, bih, Whh, bhh);

  k_hm<<<GRID_W, 256>>>(hB_p, msW, msb);
  k_agg<<<GRID_AGG, 256>>>();
  k_gru<<<GRID_GRU, 256, GRU_SMEM>>>(hB_p, hA_p, Wih, bih, Whh, bhh);

  k_hm<<<GRID_W, 256>>>(hA_p, msW, msb);
  k_agg<<<GRID_AGG, 256>>>();
  k_gru<<<GRID_GRU, 256, GRU_SMEM>>>(hA_p, hB_p, Wih, bih, Whh, bhh);

  k_AB<<<GRID_W, 256>>>(hB_p, dW1, db1);
  k_dec<<<(MM + 255)/256, 256>>>(ea, out, dW1, dW2, db2, dW3, db3);
}

// round 4
// speedup vs baseline: 1.7012x; 1.1705x over previous
#include <cuda_runtime.h>
#include <math.h>

#define NN 50000
#define MM 1250000
#define H  64
#define EF 16
#define NIF 23
#define EWH 32

typedef unsigned long long ull;

__device__ float g_hA[NN*H];
__device__ float g_hB[NN*H];
__device__ float g_hm[NN*H];
__device__ float g_agg[NN*H];
__device__ float g_Ad[NN*H];
__device__ float g_Bd[NN*H];
__device__ float g_alpha[MM];
__device__ int   g_src[MM];
__device__ int   g_dst[MM];
__device__ int2  g_csr[MM];
__device__ int   g_cnt[NN];
__device__ int   g_rowptr[NN+1];
__device__ int   g_cursor[NN];
__device__ int   g_is64;
__device__ int   g_bsum[256];
__device__ int   g_boff[256];
// packed weight tables (built once per launch by k_packw)
__device__ ull g_Wih_p[64*3*32];   // idx=(k*3+g)*32+jp : (W[(g*64+jp)*64+k], W[(g*64+jp+32)*64+k])
__device__ ull g_Whh_p[64*3*32];
__device__ ull g_W2_p[64*16];      // idx=k*16+jp : (W2[jp*64+k], W2[(jp+16)*64+k])
__device__ ull g_W1e_p[5*32];      // idx=k*32+jp : (W1[jp*133+128+k], W1[(jp+32)*133+128+k])

__device__ __forceinline__ float sigf(float x){ return 1.f/(1.f+__expf(-x)); }

__device__ __forceinline__ ull ffma2(ull a, ull b, ull c){
  ull d;
  asm("fma.rn.f32x2 %0, %1, %2, %3;" : "=l"(d) : "l"(a), "l"(b), "l"(c));
  return d;
}
__device__ __forceinline__ ull dup2(float v){
  ull r; asm("mov.b64 %0, {%1, %1};" : "=l"(r) : "f"(v)); return r;
}
__device__ __forceinline__ ull pk2(float lo, float hi){
  ull r; asm("mov.b64 %0, {%1, %2};" : "=l"(r) : "f"(lo), "f"(hi)); return r;
}
__device__ __forceinline__ void unpk2(ull p, float& lo, float& hi){
  asm("mov.b64 {%0, %1}, %2;" : "=f"(lo), "=f"(hi) : "l"(p));
}

__global__ void k_zero(){
  int i = blockIdx.x*blockDim.x + threadIdx.x;
  if (i < NN) g_cnt[i] = 0;
}

__global__ void k_detect(const int* __restrict__ ei){
  __shared__ int nz;
  if (threadIdx.x == 0) nz = 0;
  __syncthreads();
  int c = 0;
  for (int i = threadIdx.x; i < 4096; i += blockDim.x) c += (ei[2*i+1] != 0);
  if (c) atomicAdd(&nz, 1);
  __syncthreads();
  if (threadIdx.x == 0) g_is64 = (nz == 0);
}

// pack weight tables
__global__ void k_packw(const float* __restrict__ Wih, const float* __restrict__ Whh,
                        const float* __restrict__ W2, const float* __restrict__ W1){
  int i = blockIdx.x*blockDim.x + threadIdx.x;
  int tot = 6144 + 6144 + 1024 + 160;
  if (i >= tot) return;
  if (i < 6144){
    int jp = i & 31, r = i >> 5, g = r % 3, k = r / 3;
    g_Wih_p[i] = pk2(Wih[(g*64+jp)*64 + k], Wih[(g*64+jp+32)*64 + k]);
  } else if (i < 12288){
    int q = i - 6144;
    int jp = q & 31, r = q >> 5, g = r % 3, k = r / 3;
    g_Whh_p[q] = pk2(Whh[(g*64+jp)*64 + k], Whh[(g*64+jp+32)*64 + k]);
  } else if (i < 13312){
    int q = i - 12288;
    int jp = q & 15, k = q >> 4;
    g_W2_p[q] = pk2(W2[jp*64 + k], W2[(jp+16)*64 + k]);
  } else {
    int q = i - 13312;
    int jp = q & 31, k = q >> 5;
    g_W1e_p[q] = pk2(W1[jp*133 + 128 + k], W1[(jp+32)*133 + 128 + k]);
  }
}

__global__ void k_prep(const void* __restrict__ ei, const float* __restrict__ ea,
                       const float* __restrict__ u,
                       const float* __restrict__ W1, const float* __restrict__ b1,
                       const float* __restrict__ W2, const float* __restrict__ b2){
  __shared__ float sW[EWH*EF], sb1[EWH], sW2[EWH], su[11], sb2;
  int t = threadIdx.x;
  for (int i = t; i < EWH*EF; i += blockDim.x) sW[i] = W1[i];
  if (t < EWH){ sb1[t] = b1[t]; sW2[t] = W2[t]; }
  if (t < 11) su[t] = u[t];
  if (t == 0) sb2 = b2[0];
  __syncthreads();
  int e = blockIdx.x*blockDim.x + t;
  if (e >= MM) return;
  int s, d;
  if (g_is64){
    const long long* p = (const long long*)ei;
    s = (int)p[e]; d = (int)p[MM + e];
  } else {
    const int* p = (const int*)ei;
    s = p[e]; d = p[MM + e];
  }
  g_src[e] = s; g_dst[e] = d;
  atomicAdd(&g_cnt[d], 1);
  float f[EF];
  #pragma unroll
  for (int k = 0; k < 5; k++) f[k] = ea[e*5 + k];
  #pragma unroll
  for (int k = 0; k < 11; k++) f[5+k] = su[k];
  float acc = sb2;
  #pragma unroll
  for (int i = 0; i < EWH; i++){
    float a = sb1[i];
    #pragma unroll
    for (int k = 0; k < EF; k++) a = fmaf(f[k], sW[i*EF + k], a);
    acc = fmaf(fmaxf(a, 0.f), sW2[i], acc);
  }
  g_alpha[e] = sigf(acc);
}

// hierarchical scan: 196 blocks of 256
#define SCB 196
__global__ void k_scan1(){
  int b = blockIdx.x, t = threadIdx.x;
  int i = b*256 + t;
  int v = (i < NN) ? g_cnt[i] : 0;
  __shared__ int ws[8];
  int lane = t & 31, wid = t >> 5;
  #pragma unroll
  for (int o = 16; o >= 1; o >>= 1) v += __shfl_down_sync(~0u, v, o);
  if (lane == 0) ws[wid] = v;
  __syncthreads();
  if (t == 0){
    int s = 0;
    #pragma unroll
    for (int w = 0; w < 8; w++) s += ws[w];
    g_bsum[b] = s;
  }
}
__global__ void k_scan2(){
  int t = threadIdx.x;
  int v = (t < SCB) ? g_bsum[t] : 0;
  int lane = t & 31, wid = t >> 5;
  __shared__ int ws[8], wo[8];
  int x = v;
  #pragma unroll
  for (int o = 1; o < 32; o <<= 1){ int u = __shfl_up_sync(~0u, x, o); if (lane >= o) x += u; }
  if (lane == 31) ws[wid] = x;
  __syncthreads();
  if (t == 0){
    int s = 0;
    #pragma unroll
    for (int w = 0; w < 8; w++){ wo[w] = s; s += ws[w]; }
  }
  __syncthreads();
  g_boff[t] = x - v + wo[wid];
}
__global__ void k_scan3(){
  int b = blockIdx.x, t = threadIdx.x;
  int i = b*256 + t;
  int v = (i < NN) ? g_cnt[i] : 0;
  int lane = t & 31, wid = t >> 5;
  __shared__ int ws[8], wo[8];
  int x = v;
  #pragma unroll
  for (int o = 1; o < 32; o <<= 1){ int u = __shfl_up_sync(~0u, x, o); if (lane >= o) x += u; }
  if (lane == 31) ws[wid] = x;
  __syncthreads();
  if (t == 0){
    int s = 0;
    #pragma unroll
    for (int w = 0; w < 8; w++){ wo[w] = s; s += ws[w]; }
  }
  __syncthreads();
  int excl = x - v + wo[wid] + g_boff[b];
  if (i < NN){ g_cursor[i] = excl; g_rowptr[i+1] = excl + v; }
  if (i == 0) g_rowptr[0] = 0;
}

__global__ void k_fill(){
  int e = blockIdx.x*blockDim.x + threadIdx.x;
  if (e >= MM) return;
  int d = g_dst[e];
  int p = atomicAdd(&g_cursor[d], 1);
  g_csr[p] = make_int2(g_src[e], __float_as_int(g_alpha[e]));
}

__global__ void k_h(const float* __restrict__ x, const float* __restrict__ u,
                    const float* __restrict__ Wi, const float* __restrict__ bi){
  __shared__ float sW[H*NIF], su[11], sb[H];
  int t = threadIdx.x;
  for (int i = t; i < H*NIF; i += blockDim.x) sW[i] = Wi[i];
  if (t < 11) su[t] = u[t];
  if (t < H) sb[t] = bi[t];
  __syncthreads();
  int idx = blockIdx.x*blockDim.x + t;
  if (idx >= NN*H) return;
  int node = idx >> 6, j = idx & 63;
  const float* w = &sW[j*NIF];
  const float* xr = &x[node*12];
  float acc = sb[j];
  #pragma unroll
  for (int k = 0; k < 12; k++) acc = fmaf(xr[k], w[k], acc);
  #pragma unroll
  for (int k = 0; k < 11; k++) acc = fmaf(su[k], w[12+k], acc);
  g_hA[idx] = tanhf(acc);
}

__global__ void k_hm(const float* __restrict__ hin,
                     const float* __restrict__ W, const float* __restrict__ b){
  __shared__ float sWt[H*65], sb[H];
  int t = threadIdx.x;
  for (int i = t; i < H*H; i += blockDim.x){ int j = i >> 6, k = i & 63; sWt[k*65 + j] = W[i]; }
  if (t < H) sb[t] = b[t];
  __syncthreads();
  int lane = t & 31;
  int wg = (blockIdx.x*blockDim.x + t) >> 5;
  int nw = (gridDim.x*blockDim.x) >> 5;
  for (int n = wg; n < NN; n += nw){
    float v0 = hin[(n<<6) + lane], v1 = hin[(n<<6) + 32 + lane];
    float a0 = sb[lane], a1 = sb[32 + lane];
    #pragma unroll
    for (int k = 0; k < 32; k++){
      float hk = __shfl_sync(0xffffffffu, v0, k);
      a0 = fmaf(hk, sWt[k*65 + lane], a0);
      a1 = fmaf(hk, sWt[k*65 + 32 + lane], a1);
    }
    #pragma unroll
    for (int k = 0; k < 32; k++){
      float hk = __shfl_sync(0xffffffffu, v1, k);
      a0 = fmaf(hk, sWt[(32+k)*65 + lane], a0);
      a1 = fmaf(hk, sWt[(32+k)*65 + 32 + lane], a1);
    }
    g_hm[(n<<6) + lane]      = fmaxf(a0, 0.f);
    g_hm[(n<<6) + 32 + lane] = fmaxf(a1, 0.f);
  }
}

__global__ void k_agg(){
  int w = (blockIdx.x*blockDim.x + threadIdx.x) >> 5;
  int lane = threadIdx.x & 31;
  if (w >= NN) return;
  int beg = g_rowptr[w], end = g_rowptr[w+1];
  float a0 = 0.f, a1 = 0.f;
  int i = beg;
  for (; i + 1 < end; i += 2){
    int2 e0 = g_csr[i], e1 = g_csr[i+1];
    float al0 = __int_as_float(e0.y), al1 = __int_as_float(e1.y);
    const float* p0 = &g_hm[(size_t)e0.x << 6];
    const float* p1 = &g_hm[(size_t)e1.x << 6];
    a0 = fmaf(al0, p0[lane], a0); a1 = fmaf(al0, p0[lane+32], a1);
    a0 = fmaf(al1, p1[lane], a0); a1 = fmaf(al1, p1[lane+32], a1);
  }
  if (i < end){
    int2 e0 = g_csr[i];
    float al0 = __int_as_float(e0.y);
    const float* p0 = &g_hm[(size_t)e0.x << 6];
    a0 = fmaf(al0, p0[lane], a0); a1 = fmaf(al0, p0[lane+32], a1);
  }
  float inv = 1.f / fmaxf((float)(end - beg), 1.f);
  g_agg[(w<<6) + lane]      = a0 * inv;
  g_agg[(w<<6) + 32 + lane] = a1 * inv;
}

// GRU: warp covers all 64 j as 32 packed (j, j+32) pairs; GNB nodes per warp
#define GNB 4
#define GRU_SMEM (2*6144*8)
__global__ void __launch_bounds__(256,2) k_gru(
    const float* __restrict__ hin, float* __restrict__ hout,
    const float* __restrict__ bih, const float* __restrict__ bhh){
  extern __shared__ ull sw[];
  ull* sWi = sw;           // 6144
  ull* sWh = sw + 6144;
  __shared__ float sbi[192], sbh[192];
  int t = threadIdx.x;
  for (int i = t; i < 6144; i += 256){ sWi[i] = g_Wih_p[i]; sWh[i] = g_Whh_p[i]; }
  for (int i = t; i < 192; i += 256){ sbi[i] = bih[i]; sbh[i] = bhh[i]; }
  __syncthreads();
  int w = t >> 5, lane = t & 31;
  int nchunk = (NN + 31) / 32;
  for (int c = blockIdx.x; c < nchunk; c += gridDim.x){
    int nbase = c*32 + w*GNB;
    float ra0[GNB], ra1[GNB], rh0[GNB], rh1[GNB];
    #pragma unroll
    for (int i = 0; i < GNB; i++){
      int n = min(nbase + i, NN - 1);
      ra0[i] = g_agg[(n<<6) + lane];  ra1[i] = g_agg[(n<<6) + 32 + lane];
      rh0[i] = hin[(n<<6) + lane];    rh1[i] = hin[(n<<6) + 32 + lane];
    }
    ull R[GNB], Z[GNB], Ng[GNB], Rh[GNB], Zh[GNB], Nh[GNB];
    #pragma unroll
    for (int i = 0; i < GNB; i++){ R[i]=Z[i]=Ng[i]=Rh[i]=Zh[i]=Nh[i]=0ull; }
    #pragma unroll 4
    for (int k = 0; k < 32; k++){
      ull wir = sWi[(k*3+0)*32 + lane], wiz = sWi[(k*3+1)*32 + lane], win = sWi[(k*3+2)*32 + lane];
      ull whr = sWh[(k*3+0)*32 + lane], whz = sWh[(k*3+1)*32 + lane], whn = sWh[(k*3+2)*32 + lane];
      #pragma unroll
      for (int i = 0; i < GNB; i++){
        ull av = dup2(__shfl_sync(~0u, ra0[i], k));
        ull hv = dup2(__shfl_sync(~0u, rh0[i], k));
        R[i]  = ffma2(av, wir, R[i]);  Z[i]  = ffma2(av, wiz, Z[i]);  Ng[i] = ffma2(av, win, Ng[i]);
        Rh[i] = ffma2(hv, whr, Rh[i]); Zh[i] = ffma2(hv, whz, Zh[i]); Nh[i] = ffma2(hv, whn, Nh[i]);
      }
    }
    #pragma unroll 4
    for (int k = 32; k < 64; k++){
      ull wir = sWi[(k*3+0)*32 + lane], wiz = sWi[(k*3+1)*32 + lane], win = sWi[(k*3+2)*32 + lane];
      ull whr = sWh[(k*3+0)*32 + lane], whz = sWh[(k*3+1)*32 + lane], whn = sWh[(k*3+2)*32 + lane];
      #pragma unroll
      for (int i = 0; i < GNB; i++){
        ull av = dup2(__shfl_sync(~0u, ra1[i], k - 32));
        ull hv = dup2(__shfl_sync(~0u, rh1[i], k - 32));
        R[i]  = ffma2(av, wir, R[i]);  Z[i]  = ffma2(av, wiz, Z[i]);  Ng[i] = ffma2(av, win, Ng[i]);
        Rh[i] = ffma2(hv, whr, Rh[i]); Zh[i] = ffma2(hv, whz, Zh[i]); Nh[i] = ffma2(hv, whn, Nh[i]);
      }
    }
    float birL = sbi[lane],     birH = sbi[lane+32];
    float bizL = sbi[64+lane],  bizH = sbi[96+lane];
    float binL = sbi[128+lane], binH = sbi[160+lane];
    float bhrL = sbh[lane],     bhrH = sbh[lane+32];
    float bhzL = sbh[64+lane],  bhzH = sbh[96+lane];
    float bhnL = sbh[128+lane], bhnH = sbh[160+lane];
    #pragma unroll
    for (int i = 0; i < GNB; i++){
      int n = nbase + i;
      if (n >= NN) break;
      float rL,rH,zL,zH,ngL,ngH, aL,aH,bL,bH;
      unpk2(R[i],  aL, aH); unpk2(Rh[i], bL, bH);
      rL = sigf(aL + birL + bL + bhrL); rH = sigf(aH + birH + bH + bhrH);
      unpk2(Z[i],  aL, aH); unpk2(Zh[i], bL, bH);
      zL = sigf(aL + bizL + bL + bhzL); zH = sigf(aH + bizH + bH + bhzH);
      unpk2(Ng[i], aL, aH); unpk2(Nh[i], bL, bH);
      ngL = tanhf(aL + binL + rL*(bL + bhnL));
      ngH = tanhf(aH + binH + rH*(bH + bhnH));
      hout[(n<<6) + lane]      = (1.f - zL)*ngL + zL*rh0[i];
      hout[(n<<6) + 32 + lane] = (1.f - zH)*ngH + zH*rh1[i];
    }
  }
}

__global__ void k_AB(const float* __restrict__ hin,
                     const float* __restrict__ W1, const float* __restrict__ b1){
  __shared__ float sAt[H*65], sBt[H*65], sb[H];
  int t = threadIdx.x;
  for (int i = t; i < H*H; i += blockDim.x){
    int j = i >> 6, k = i & 63;
    sAt[k*65 + j] = W1[j*133 + k];
    sBt[k*65 + j] = W1[j*133 + 64 + k];
  }
  if (t < H) sb[t] = b1[t];
  __syncthreads();
  int lane = t & 31;
  int wg = (blockIdx.x*blockDim.x + t) >> 5;
  int nw = (gridDim.x*blockDim.x) >> 5;
  for (int n = wg; n < NN; n += nw){
    float v0 = hin[(n<<6) + lane], v1 = hin[(n<<6) + 32 + lane];
    float a0 = sb[lane], a1 = sb[32+lane], b0 = 0.f, b1v = 0.f;
    #pragma unroll
    for (int k = 0; k < 32; k++){
      float hk = __shfl_sync(0xffffffffu, v0, k);
      a0 = fmaf(hk, sAt[k*65 + lane], a0);      a1 = fmaf(hk, sAt[k*65 + 32 + lane], a1);
      b0 = fmaf(hk, sBt[k*65 + lane], b0);      b1v = fmaf(hk, sBt[k*65 + 32 + lane], b1v);
    }
    #pragma unroll
    for (int k = 0; k < 32; k++){
      float hk = __shfl_sync(0xffffffffu, v1, k);
      a0 = fmaf(hk, sAt[(32+k)*65 + lane], a0); a1 = fmaf(hk, sAt[(32+k)*65 + 32 + lane], a1);
      b0 = fmaf(hk, sBt[(32+k)*65 + lane], b0); b1v = fmaf(hk, sBt[(32+k)*65 + 32 + lane], b1v);
    }
    g_Ad[(n<<6) + lane]      = a0;  g_Ad[(n<<6) + 32 + lane] = a1;
    g_Bd[(n<<6) + lane]      = b0;  g_Bd[(n<<6) + 32 + lane] = b1v;
  }
}

// decoder with f32x2 packed layers 1+2
__global__ void __launch_bounds__(256) k_dec(
    const float* __restrict__ ea, float* __restrict__ out,
    const float* __restrict__ b2, const float* __restrict__ W3,
    const float* __restrict__ b3){
  __shared__ __align__(16) ull sW1[160];   // [k][jp] pairs (j, j+32)
  __shared__ __align__(16) ull sW2[1024];  // [k][jp] pairs (j, j+16)
  __shared__ float4 sW3[32];               // row-major W3 [4][8]
  __shared__ float sb2[32], sb3[4];
  int t = threadIdx.x;
  for (int i = t; i < 160;  i += blockDim.x) sW1[i] = g_W1e_p[i];
  for (int i = t; i < 1024; i += blockDim.x) sW2[i] = g_W2_p[i];
  {
    float* p3 = (float*)sW3;
    for (int i = t; i < 128; i += blockDim.x) p3[i] = W3[i];
  }
  if (t < 32) sb2[t] = b2[t];
  if (t < 4)  sb3[t] = b3[t];
  __syncthreads();
  int e = blockIdx.x*blockDim.x + t;
  if (e >= MM) return;
  int s = g_src[e], d = g_dst[e];
  const float4* pA = (const float4*)&g_Ad[(size_t)s << 6];
  const float4* pB = (const float4*)&g_Bd[(size_t)d << 6];
  // s1p[jp] = (A+B)[jp], (A+B)[jp+32]
  ull s1p[32];
  #pragma unroll
  for (int q = 0; q < 8; q++){
    float4 aL = __ldg(&pA[q]),   bL = __ldg(&pB[q]);
    float4 aH = __ldg(&pA[q+8]), bH = __ldg(&pB[q+8]);
    s1p[4*q]   = pk2(aL.x + bL.x, aH.x + bH.x);
    s1p[4*q+1] = pk2(aL.y + bL.y, aH.y + bH.y);
    s1p[4*q+2] = pk2(aL.z + bL.z, aH.z + bH.z);
    s1p[4*q+3] = pk2(aL.w + bL.w, aH.w + bH.w);
  }
  // layer 1 edge part (packed)
  const ulonglong2* w1 = (const ulonglong2*)sW1;
  #pragma unroll
  for (int k = 0; k < 5; k++){
    ull ev = dup2(ea[e*5 + k]);
    #pragma unroll
    for (int q = 0; q < 16; q++){
      ulonglong2 wq = w1[k*16 + q];
      s1p[2*q]   = ffma2(ev, wq.x, s1p[2*q]);
      s1p[2*q+1] = ffma2(ev, wq.y, s1p[2*q+1]);
    }
  }
  // relu -> scalars
  float s1[64];
  #pragma unroll
  for (int jp = 0; jp < 32; jp++){
    float lo, hi; unpk2(s1p[jp], lo, hi);
    s1[jp] = fmaxf(lo, 0.f); s1[jp+32] = fmaxf(hi, 0.f);
  }
  // layer 2 (packed pairs j, j+16)
  ull a2p[16];
  #pragma unroll
  for (int jp = 0; jp < 16; jp++) a2p[jp] = pk2(sb2[jp], sb2[jp+16]);
  const ulonglong2* w2 = (const ulonglong2*)sW2;
  #pragma unroll 8
  for (int k = 0; k < 64; k++){
    ull sd = dup2(s1[k]);
    #pragma unroll
    for (int q = 0; q < 8; q++){
      ulonglong2 wq = w2[k*8 + q];
      a2p[2*q]   = ffma2(sd, wq.x, a2p[2*q]);
      a2p[2*q+1] = ffma2(sd, wq.y, a2p[2*q+1]);
    }
  }
  float a2[32];
  #pragma unroll
  for (int jp = 0; jp < 16; jp++){
    float lo, hi; unpk2(a2p[jp], lo, hi);
    a2[jp] = fmaxf(lo, 0.f); a2[jp+16] = fmaxf(hi, 0.f);
  }
  // layer 3 scalar
  float o[4];
  #pragma unroll
  for (int j = 0; j < 4; j++){
    float acc = sb3[j];
    #pragma unroll
    for (int q = 0; q < 8; q++){
      float4 wv = sW3[j*8 + q];
      acc = fmaf(a2[4*q],   wv.x, acc);
      acc = fmaf(a2[4*q+1], wv.y, acc);
      acc = fmaf(a2[4*q+2], wv.z, acc);
      acc = fmaf(a2[4*q+3], wv.w, acc);
    }
    o[j] = acc;
  }
  ((float4*)out)[e] = make_float4(o[0], o[1], o[2], o[3]);
}

extern "C" void kernel_launch(void* const* d_in, const int* in_sizes, int n_in,
                              void* d_out, int out_size){
  (void)in_sizes; (void)n_in; (void)out_size;
  const float* x    = (const float*)d_in[0];
  const void*  ei   = d_in[1];
  const float* ea   = (const float*)d_in[2];
  const float* u    = (const float*)d_in[3];
  const float* Win  = (const float*)d_in[4];
  const float* bin  = (const float*)d_in[5];
  const float* eW1  = (const float*)d_in[6];
  const float* eb1  = (const float*)d_in[7];
  const float* eW2  = (const float*)d_in[8];
  const float* eb2  = (const float*)d_in[9];
  const float* msW  = (const float*)d_in[10];
  const float* msb  = (const float*)d_in[11];
  const float* Wih  = (const float*)d_in[12];
  const float* bih  = (const float*)d_in[13];
  const float* Whh  = (const float*)d_in[14];
  const float* bhh  = (const float*)d_in[15];
  const float* dW1  = (const float*)d_in[16];
  const float* db1  = (const float*)d_in[17];
  const float* dW2  = (const float*)d_in[18];
  const float* db2  = (const float*)d_in[19];
  const float* dW3  = (const float*)d_in[20];
  const float* db3  = (const float*)d_in[21];
  float* out = (float*)d_out;

  static int attr_done = 0;
  if (!attr_done){
    cudaFuncSetAttribute(k_gru, cudaFuncAttributeMaxDynamicSharedMemorySize, GRU_SMEM);
    attr_done = 1;
  }

  k_detect<<<1, 256>>>((const int*)ei);
  k_zero<<<(NN + 255)/256, 256>>>();
  k_packw<<<(13472 + 255)/256, 256>>>(Wih, Whh, dW2, dW1);
  k_prep<<<(MM + 255)/256, 256>>>(ei, ea, u, eW1, eb1, eW2, eb2);
  k_scan1<<<SCB, 256>>>();
  k_scan2<<<1, 256>>>();
  k_scan3<<<SCB, 256>>>();
  k_fill<<<(MM + 255)/256, 256>>>();
  k_h<<<(NN*H + 255)/256, 256>>>(x, u, Win, bin);

  const int GRID_W   = 1184;
  const int GRID_AGG = (NN*32 + 255)/256;
  const int GRID_GRU = 296;

  float *hA_p = nullptr, *hB_p = nullptr;
  cudaGetSymbolAddress((void**)&hA_p, g_hA);
  cudaGetSymbolAddress((void**)&hB_p, g_hB);

  k_hm<<<GRID_W, 256>>>(hA_p, msW, msb);
  k_agg<<<GRID_AGG, 256>>>();
  k_gru<<<GRID_GRU, 256, GRU_SMEM>>>(hA_p, hB_p, bih, bhh);

  k_hm<<<GRID_W, 256>>>(hB_p, msW, msb);
  k_agg<<<GRID_AGG, 256>>>();
  k_gru<<<GRID_GRU, 256, GRU_SMEM>>>(hB_p, hA_p, bih, bhh);

  k_hm<<<GRID_W, 256>>>(hA_p, msW, msb);
  k_agg<<<GRID_AGG, 256>>>();
  k_gru<<<GRID_GRU, 256, GRU_SMEM>>>(hA_p, hB_p, bih, bhh);

  k_AB<<<GRID_W, 256>>>(hB_p, dW1, db1);
  k_dec<<<(MM + 255)/256, 256>>>(ea, out, db2, dW3, db3);
}

// round 5
// speedup vs baseline: 1.7711x; 1.0411x over previous
#include <cuda_runtime.h>
#include <cuda_fp16.h>
#include <math.h>

#define NN 50000
#define MM 1250000
#define H  64

typedef unsigned long long ull;

__device__ float g_hA[NN*H];
__device__ float g_hB[NN*H];
__device__ __half2 g_hmh[NN*32];
__device__ float g_agg[NN*H];
__device__ float g_Ad[NN*H];
__device__ float g_Bd[NN*H];
__device__ int   g_src[MM];
__device__ int   g_dst[MM];
__device__ int   g_rank[MM];
__device__ int2  g_sa[MM];
__device__ int2  g_csr[MM];
__device__ int   g_cnt[NN];
__device__ int   g_rowptr[NN+1];
__device__ int   g_is64;
__device__ int   g_bsum[256];
__device__ int   g_boff[256];
// packed tables
__device__ ull g_Wih_p[64*3*32];
__device__ ull g_Whh_p[64*3*32];
__device__ ull g_W2_p[64*16];
__device__ ull g_W1e_p[5*32];
__device__ ull g_Whm_p[64*32];     // (msW[2l*64+k], msW[(2l+1)*64+k]) at k*32+l
__device__ ull g_We_p[5*16];       // alpha-MLP layer1 pairs (i,i+16) at k*16+i
__device__ float g_b1e[32];        // alpha-MLP bias with u folded
__device__ float g_W2e[32];
__device__ float g_bhe[64];        // input-proj bias with u folded

__device__ __forceinline__ float sigf(float x){ return 1.f/(1.f+__expf(-x)); }
__device__ __forceinline__ ull ffma2(ull a, ull b, ull c){
  ull d; asm("fma.rn.f32x2 %0, %1, %2, %3;" : "=l"(d) : "l"(a), "l"(b), "l"(c)); return d;
}
__device__ __forceinline__ ull dup2(float v){
  ull r; asm("mov.b64 %0, {%1, %1};" : "=l"(r) : "f"(v)); return r;
}
__device__ __forceinline__ ull pk2(float lo, float hi){
  ull r; asm("mov.b64 %0, {%1, %2};" : "=l"(r) : "f"(lo), "f"(hi)); return r;
}
__device__ __forceinline__ void unpk2(ull p, float& lo, float& hi){
  asm("mov.b64 {%0, %1}, %2;" : "=f"(lo), "=f"(hi) : "l"(p));
}

__global__ void k_zero(){
  int i = blockIdx.x*blockDim.x + threadIdx.x;
  if (i < NN) g_cnt[i] = 0;
}

__global__ void k_detect(const int* __restrict__ ei){
  __shared__ int nz;
  if (threadIdx.x == 0) nz = 0;
  __syncthreads();
  int c = 0;
  for (int i = threadIdx.x; i < 4096; i += blockDim.x) c += (ei[2*i+1] != 0);
  if (c) atomicAdd(&nz, 1);
  __syncthreads();
  if (threadIdx.x == 0) g_is64 = (nz == 0);
}

__global__ void k_packw(const float* __restrict__ Wih, const float* __restrict__ Whh,
                        const float* __restrict__ W2, const float* __restrict__ W1){
  int i = blockIdx.x*blockDim.x + threadIdx.x;
  if (i < 6144){
    int jp = i & 31, r = i >> 5, g = r % 3, k = r / 3;
    g_Wih_p[i] = pk2(Wih[(g*64+jp)*64 + k], Wih[(g*64+jp+32)*64 + k]);
    int q = i;
    g_Whh_p[q] = pk2(Whh[(g*64+jp)*64 + k], Whh[(g*64+jp+32)*64 + k]);
  } else if (i < 7168){
    int q = i - 6144;
    int jp = q & 15, k = q >> 4;
    g_W2_p[q] = pk2(W2[jp*64 + k], W2[(jp+16)*64 + k]);
  } else if (i < 7328){
    int q = i - 7168;
    int jp = q & 31, k = q >> 5;
    g_W1e_p[q] = pk2(W1[jp*133 + 128 + k], W1[(jp+32)*133 + 128 + k]);
  }
}

// pack msg weights, alpha-MLP with u folded, input-proj bias with u folded
__global__ void k_packw2(const float* __restrict__ msW,
                         const float* __restrict__ eW1, const float* __restrict__ eb1,
                         const float* __restrict__ eW2,
                         const float* __restrict__ Win, const float* __restrict__ bin,
                         const float* __restrict__ u){
  int i = blockIdx.x*blockDim.x + threadIdx.x;
  if (i < 2048){
    int l = i & 31, k = i >> 5;
    g_Whm_p[i] = pk2(msW[(2*l)*64 + k], msW[(2*l+1)*64 + k]);
  } else if (i < 2128){
    int q = i - 2048;
    int ip = q & 15, k = q >> 4;
    g_We_p[q] = pk2(eW1[ip*16 + k], eW1[(ip+16)*16 + k]);
  } else if (i < 2160){
    int q = i - 2128;
    float acc = eb1[q];
    #pragma unroll
    for (int k = 0; k < 11; k++) acc = fmaf(u[k], eW1[q*16 + 5 + k], acc);
    g_b1e[q] = acc;
    g_W2e[q] = eW2[q];
  } else if (i < 2224){
    int j = i - 2160;
    float acc = bin[j];
    #pragma unroll
    for (int k = 0; k < 11; k++) acc = fmaf(u[k], Win[j*23 + 12 + k], acc);
    g_bhe[j] = acc;
  }
}

__global__ void __launch_bounds__(256) k_prep(
    const void* __restrict__ ei, const float* __restrict__ ea,
    const float* __restrict__ b2){
  __shared__ float sEA[1280];
  __shared__ ull sWe[80], sB1[16];
  __shared__ float sW2[32];
  __shared__ float sb2;
  int t = threadIdx.x;
  int base = blockIdx.x*256;
  for (int i = t; i < 80; i += 256) sWe[i] = g_We_p[i];
  if (t < 16) sB1[t] = pk2(g_b1e[t], g_b1e[t+16]);
  if (t < 32) sW2[t] = g_W2e[t];
  if (t == 0) sb2 = b2[0];
  {
    int lim = MM*5 - base*5;
    for (int i = t; i < 1280 && i < lim; i += 256) sEA[i] = ea[base*5 + i];
  }
  __syncthreads();
  int e = base + t;
  if (e >= MM) return;
  int s, d;
  if (g_is64){
    const long long* p = (const long long*)ei;
    s = (int)p[e]; d = (int)p[MM + e];
  } else {
    const int* p = (const int*)ei;
    s = p[e]; d = p[MM + e];
  }
  g_src[e] = s; g_dst[e] = d;
  g_rank[e] = atomicAdd(&g_cnt[d], 1);
  float f[5];
  #pragma unroll
  for (int k = 0; k < 5; k++) f[k] = sEA[t*5 + k];
  ull ap[16];
  #pragma unroll
  for (int i = 0; i < 16; i++) ap[i] = sB1[i];
  #pragma unroll
  for (int k = 0; k < 5; k++){
    ull fv = dup2(f[k]);
    #pragma unroll
    for (int i = 0; i < 16; i++) ap[i] = ffma2(fv, sWe[k*16 + i], ap[i]);
  }
  float acc = sb2;
  #pragma unroll
  for (int i = 0; i < 16; i++){
    float lo, hi; unpk2(ap[i], lo, hi);
    acc = fmaf(fmaxf(lo, 0.f), sW2[i], acc);
    acc = fmaf(fmaxf(hi, 0.f), sW2[i+16], acc);
  }
  g_sa[e] = make_int2(s, __float_as_int(sigf(acc)));
}

#define SCB 196
__global__ void k_scan1(){
  int b = blockIdx.x, t = threadIdx.x;
  int i = b*256 + t;
  int v = (i < NN) ? g_cnt[i] : 0;
  __shared__ int ws[8];
  int lane = t & 31, wid = t >> 5;
  #pragma unroll
  for (int o = 16; o >= 1; o >>= 1) v += __shfl_down_sync(~0u, v, o);
  if (lane == 0) ws[wid] = v;
  __syncthreads();
  if (t == 0){
    int s = 0;
    #pragma unroll
    for (int w = 0; w < 8; w++) s += ws[w];
    g_bsum[b] = s;
  }
}
__global__ void k_scan2(){
  int t = threadIdx.x;
  int v = (t < SCB) ? g_bsum[t] : 0;
  int lane = t & 31, wid = t >> 5;
  __shared__ int ws[8], wo[8];
  int x = v;
  #pragma unroll
  for (int o = 1; o < 32; o <<= 1){ int u = __shfl_up_sync(~0u, x, o); if (lane >= o) x += u; }
  if (lane == 31) ws[wid] = x;
  __syncthreads();
  if (t == 0){
    int s = 0;
    #pragma unroll
    for (int w = 0; w < 8; w++){ wo[w] = s; s += ws[w]; }
  }
  __syncthreads();
  g_boff[t] = x - v + wo[wid];
}
__global__ void k_scan3(){
  int b = blockIdx.x, t = threadIdx.x;
  int i = b*256 + t;
  int v = (i < NN) ? g_cnt[i] : 0;
  int lane = t & 31, wid = t >> 5;
  __shared__ int ws[8], wo[8];
  int x = v;
  #pragma unroll
  for (int o = 1; o < 32; o <<= 1){ int u = __shfl_up_sync(~0u, x, o); if (lane >= o) x += u; }
  if (lane == 31) ws[wid] = x;
  __syncthreads();
  if (t == 0){
    int s = 0;
    #pragma unroll
    for (int w = 0; w < 8; w++){ wo[w] = s; s += ws[w]; }
  }
  __syncthreads();
  int excl = x - v + wo[wid] + g_boff[b];
  if (i < NN) g_rowptr[i+1] = excl + v;
  if (i == 0) g_rowptr[0] = 0;
}

// no atomics: position = rowptr[d] + rank
__global__ void k_fill(){
  int e = blockIdx.x*blockDim.x + threadIdx.x;
  if (e >= MM) return;
  int d = g_dst[e];
  g_csr[g_rowptr[d] + g_rank[e]] = g_sa[e];
}

__global__ void k_h(const float* __restrict__ x){
  __shared__ float sW[64*12], sb[64];
  int t = threadIdx.x;
  extern __shared__ float dummy[];
  for (int i = t; i < 64*12; i += blockDim.x){
    // load from constant-ish: W stored row-major j*23 — need Win; pass via global pack? use g_bhe for bias
    sW[i] = dummy[0]; // placeholder replaced below
  }
  (void)sW; (void)sb;
}

// real k_h (reads Win directly, bias pre-folded)
__global__ void k_h2(const float* __restrict__ x, const float* __restrict__ Win){
  __shared__ float sW[64*12], sb[64];
  int t = threadIdx.x;
  for (int i = t; i < 64*12; i += blockDim.x){ int j = i/12, k = i%12; sW[i] = Win[j*23 + k]; }
  if (t < 64) sb[t] = g_bhe[t];
  __syncthreads();
  int idx = blockIdx.x*blockDim.x + t;
  if (idx >= NN*H) return;
  int node = idx >> 6, j = idx & 63;
  const float* w = &sW[j*12];
  const float* xr = &x[node*12];
  float acc = sb[j];
  #pragma unroll
  for (int k = 0; k < 12; k++) acc = fmaf(xr[k], w[k], acc);
  g_hA[idx] = tanhf(acc);
}

// hm = relu(h@W.T+b) -> half2; lane owns feature pair (2l, 2l+1), f32x2 math
__global__ void k_hm(const float* __restrict__ hin, const float* __restrict__ b){
  __shared__ ull sW[64*32];
  __shared__ ull sbp[32];
  int t = threadIdx.x;
  for (int i = t; i < 2048; i += blockDim.x) sW[i] = g_Whm_p[i];
  if (t < 32) sbp[t] = pk2(b[2*t], b[2*t+1]);
  __syncthreads();
  int lane = t & 31;
  int wg = (blockIdx.x*blockDim.x + t) >> 5;
  int nw = (gridDim.x*blockDim.x) >> 5;
  for (int n = wg; n < NN; n += nw){
    float v0 = hin[(n<<6) + lane], v1 = hin[(n<<6) + 32 + lane];
    ull ap = sbp[lane];
    #pragma unroll 8
    for (int k = 0; k < 32; k++)
      ap = ffma2(dup2(__shfl_sync(~0u, v0, k)), sW[k*32 + lane], ap);
    #pragma unroll 8
    for (int k = 0; k < 32; k++)
      ap = ffma2(dup2(__shfl_sync(~0u, v1, k)), sW[(32+k)*32 + lane], ap);
    float lo, hi; unpk2(ap, lo, hi);
    g_hmh[n*32 + lane] = __floats2half2_rn(fmaxf(lo, 0.f), fmaxf(hi, 0.f));
  }
}

// aggregation over CSR, fp16 rows (128B/edge)
__global__ void k_agg(){
  int w = (blockIdx.x*blockDim.x + threadIdx.x) >> 5;
  int lane = threadIdx.x & 31;
  if (w >= NN) return;
  int beg = g_rowptr[w], end = g_rowptr[w+1];
  float ax = 0.f, ay = 0.f;
  int i = beg;
  for (; i + 1 < end; i += 2){
    int2 e0 = g_csr[i], e1 = g_csr[i+1];
    float al0 = __int_as_float(e0.y), al1 = __int_as_float(e1.y);
    float2 f0 = __half22float2(g_hmh[(size_t)e0.x*32 + lane]);
    float2 f1 = __half22float2(g_hmh[(size_t)e1.x*32 + lane]);
    ax = fmaf(al0, f0.x, ax); ay = fmaf(al0, f0.y, ay);
    ax = fmaf(al1, f1.x, ax); ay = fmaf(al1, f1.y, ay);
  }
  if (i < end){
    int2 e0 = g_csr[i];
    float al0 = __int_as_float(e0.y);
    float2 f0 = __half22float2(g_hmh[(size_t)e0.x*32 + lane]);
    ax = fmaf(al0, f0.x, ax); ay = fmaf(al0, f0.y, ay);
  }
  float inv = 1.f / fmaxf((float)(end - beg), 1.f);
  // features (2*lane, 2*lane+1) -> natural [n][f] layout via float2 store
  ((float2*)g_agg)[w*32 + lane] = make_float2(ax*inv, ay*inv);
}

#define GNB 4
#define GRU_SMEM (2*6144*8)
__global__ void __launch_bounds__(256,2) k_gru(
    const float* __restrict__ hin, float* __restrict__ hout,
    const float* __restrict__ bih, const float* __restrict__ bhh){
  extern __shared__ ull sw[];
  ull* sWi = sw;
  ull* sWh = sw + 6144;
  __shared__ float sbi[192], sbh[192];
  int t = threadIdx.x;
  for (int i = t; i < 6144; i += 256){ sWi[i] = g_Wih_p[i]; sWh[i] = g_Whh_p[i]; }
  for (int i = t; i < 192; i += 256){ sbi[i] = bih[i]; sbh[i] = bhh[i]; }
  __syncthreads();
  int w = t >> 5, lane = t & 31;
  int nchunk = (NN + 31) / 32;
  for (int c = blockIdx.x; c < nchunk; c += gridDim.x){
    int nbase = c*32 + w*GNB;
    float ra0[GNB], ra1[GNB], rh0[GNB], rh1[GNB];
    #pragma unroll
    for (int i = 0; i < GNB; i++){
      int n = min(nbase + i, NN - 1);
      ra0[i] = g_agg[(n<<6) + lane];  ra1[i] = g_agg[(n<<6) + 32 + lane];
      rh0[i] = hin[(n<<6) + lane];    rh1[i] = hin[(n<<6) + 32 + lane];
    }
    ull R[GNB], Z[GNB], Ng[GNB], Rh[GNB], Zh[GNB], Nh[GNB];
    #pragma unroll
    for (int i = 0; i < GNB; i++){ R[i]=Z[i]=Ng[i]=Rh[i]=Zh[i]=Nh[i]=0ull; }
    #pragma unroll 4
    for (int k = 0; k < 32; k++){
      ull wir = sWi[(k*3+0)*32 + lane], wiz = sWi[(k*3+1)*32 + lane], win = sWi[(k*3+2)*32 + lane];
      ull whr = sWh[(k*3+0)*32 + lane], whz = sWh[(k*3+1)*32 + lane], whn = sWh[(k*3+2)*32 + lane];
      #pragma unroll
      for (int i = 0; i < GNB; i++){
        ull av = dup2(__shfl_sync(~0u, ra0[i], k));
        ull hv = dup2(__shfl_sync(~0u, rh0[i], k));
        R[i]  = ffma2(av, wir, R[i]);  Z[i]  = ffma2(av, wiz, Z[i]);  Ng[i] = ffma2(av, win, Ng[i]);
        Rh[i] = ffma2(hv, whr, Rh[i]); Zh[i] = ffma2(hv, whz, Zh[i]); Nh[i] = ffma2(hv, whn, Nh[i]);
      }
    }
    #pragma unroll 4
    for (int k = 32; k < 64; k++){
      ull wir = sWi[(k*3+0)*32 + lane], wiz = sWi[(k*3+1)*32 + lane], win = sWi[(k*3+2)*32 + lane];
      ull whr = sWh[(k*3+0)*32 + lane], whz = sWh[(k*3+1)*32 + lane], whn = sWh[(k*3+2)*32 + lane];
      #pragma unroll
      for (int i = 0; i < GNB; i++){
        ull av = dup2(__shfl_sync(~0u, ra1[i], k - 32));
        ull hv = dup2(__shfl_sync(~0u, rh1[i], k - 32));
        R[i]  = ffma2(av, wir, R[i]);  Z[i]  = ffma2(av, wiz, Z[i]);  Ng[i] = ffma2(av, win, Ng[i]);
        Rh[i] = ffma2(hv, whr, Rh[i]); Zh[i] = ffma2(hv, whz, Zh[i]); Nh[i] = ffma2(hv, whn, Nh[i]);
      }
    }
    float birL = sbi[lane],     birH = sbi[lane+32];
    float bizL = sbi[64+lane],  bizH = sbi[96+lane];
    float binL = sbi[128+lane], binH = sbi[160+lane];
    float bhrL = sbh[lane],     bhrH = sbh[lane+32];
    float bhzL = sbh[64+lane],  bhzH = sbh[96+lane];
    float bhnL = sbh[128+lane], bhnH = sbh[160+lane];
    #pragma unroll
    for (int i = 0; i < GNB; i++){
      int n = nbase + i;
      if (n >= NN) break;
      float rL,rH,zL,zH,ngL,ngH, aL,aH,bL,bH;
      unpk2(R[i],  aL, aH); unpk2(Rh[i], bL, bH);
      rL = sigf(aL + birL + bL + bhrL); rH = sigf(aH + birH + bH + bhrH);
      unpk2(Z[i],  aL, aH); unpk2(Zh[i], bL, bH);
      zL = sigf(aL + bizL + bL + bhzL); zH = sigf(aH + bizH + bH + bhzH);
      unpk2(Ng[i], aL, aH); unpk2(Nh[i], bL, bH);
      ngL = tanhf(aL + binL + rL*(bL + bhnL));
      ngH = tanhf(aH + binH + rH*(bH + bhnH));
      hout[(n<<6) + lane]      = (1.f - zL)*ngL + zL*rh0[i];
      hout[(n<<6) + 32 + lane] = (1.f - zH)*ngH + zH*rh1[i];
    }
  }
}

__global__ void k_AB(const float* __restrict__ hin,
                     const float* __restrict__ W1, const float* __restrict__ b1){
  __shared__ float sAt[H*65], sBt[H*65], sb[H];
  int t = threadIdx.x;
  for (int i = t; i < H*H; i += blockDim.x){
    int j = i >> 6, k = i & 63;
    sAt[k*65 + j] = W1[j*133 + k];
    sBt[k*65 + j] = W1[j*133 + 64 + k];
  }
  if (t < H) sb[t] = b1[t];
  __syncthreads();
  int lane = t & 31;
  int wg = (blockIdx.x*blockDim.x + t) >> 5;
  int nw = (gridDim.x*blockDim.x) >> 5;
  for (int n = wg; n < NN; n += nw){
    float v0 = hin[(n<<6) + lane], v1 = hin[(n<<6) + 32 + lane];
    float a0 = sb[lane], a1 = sb[32+lane], b0 = 0.f, b1v = 0.f;
    #pragma unroll
    for (int k = 0; k < 32; k++){
      float hk = __shfl_sync(0xffffffffu, v0, k);
      a0 = fmaf(hk, sAt[k*65 + lane], a0);      a1 = fmaf(hk, sAt[k*65 + 32 + lane], a1);
      b0 = fmaf(hk, sBt[k*65 + lane], b0);      b1v = fmaf(hk, sBt[k*65 + 32 + lane], b1v);
    }
    #pragma unroll
    for (int k = 0; k < 32; k++){
      float hk = __shfl_sync(0xffffffffu, v1, k);
      a0 = fmaf(hk, sAt[(32+k)*65 + lane], a0); a1 = fmaf(hk, sAt[(32+k)*65 + 32 + lane], a1);
      b0 = fmaf(hk, sBt[(32+k)*65 + lane], b0); b1v = fmaf(hk, sBt[(32+k)*65 + 32 + lane], b1v);
    }
    g_Ad[(n<<6) + lane]      = a0;  g_Ad[(n<<6) + 32 + lane] = a1;
    g_Bd[(n<<6) + lane]      = b0;  g_Bd[(n<<6) + 32 + lane] = b1v;
  }
}

__global__ void __launch_bounds__(256) k_dec(
    const float* __restrict__ ea, float* __restrict__ out,
    const float* __restrict__ b2, const float* __restrict__ W3,
    const float* __restrict__ b3){
  __shared__ __align__(16) ull sW1[160];
  __shared__ __align__(16) ull sW2[1024];
  __shared__ float4 sW3[32];
  __shared__ float sb2[32], sb3[4];
  __shared__ float sEA[1280];
  int t = threadIdx.x;
  int base = blockIdx.x*256;
  for (int i = t; i < 160;  i += blockDim.x) sW1[i] = g_W1e_p[i];
  for (int i = t; i < 1024; i += blockDim.x) sW2[i] = g_W2_p[i];
  {
    float* p3 = (float*)sW3;
    for (int i = t; i < 128; i += blockDim.x) p3[i] = W3[i];
  }
  if (t < 32) sb2[t] = b2[t];
  if (t < 4)  sb3[t] = b3[t];
  {
    int lim = MM*5 - base*5;
    for (int i = t; i < 1280 && i < lim; i += 256) sEA[i] = ea[base*5 + i];
  }
  __syncthreads();
  int e = base + t;
  if (e >= MM) return;
  int s = g_src[e], d = g_dst[e];
  const float4* pA = (const float4*)&g_Ad[(size_t)s << 6];
  const float4* pB = (const float4*)&g_Bd[(size_t)d << 6];
  ull s1p[32];
  #pragma unroll
  for (int q = 0; q < 8; q++){
    float4 aL = __ldg(&pA[q]),   bL = __ldg(&pB[q]);
    float4 aH = __ldg(&pA[q+8]), bH = __ldg(&pB[q+8]);
    s1p[4*q]   = pk2(aL.x + bL.x, aH.x + bH.x);
    s1p[4*q+1] = pk2(aL.y + bL.y, aH.y + bH.y);
    s1p[4*q+2] = pk2(aL.z + bL.z, aH.z + bH.z);
    s1p[4*q+3] = pk2(aL.w + bL.w, aH.w + bH.w);
  }
  const ulonglong2* w1 = (const ulonglong2*)sW1;
  #pragma unroll
  for (int k = 0; k < 5; k++){
    ull ev = dup2(sEA[t*5 + k]);
    #pragma unroll
    for (int q = 0; q < 16; q++){
      ulonglong2 wq = w1[k*16 + q];
      s1p[2*q]   = ffma2(ev, wq.x, s1p[2*q]);
      s1p[2*q+1] = ffma2(ev, wq.y, s1p[2*q+1]);
    }
  }
  float s1[64];
  #pragma unroll
  for (int jp = 0; jp < 32; jp++){
    float lo, hi; unpk2(s1p[jp], lo, hi);
    s1[jp] = fmaxf(lo, 0.f); s1[jp+32] = fmaxf(hi, 0.f);
  }
  ull a2p[16];
  #pragma unroll
  for (int jp = 0; jp < 16; jp++) a2p[jp] = pk2(sb2[jp], sb2[jp+16]);
  const ulonglong2* w2 = (const ulonglong2*)sW2;
  #pragma unroll 8
  for (int k = 0; k < 64; k++){
    ull sd = dup2(s1[k]);
    #pragma unroll
    for (int q = 0; q < 8; q++){
      ulonglong2 wq = w2[k*8 + q];
      a2p[2*q]   = ffma2(sd, wq.x, a2p[2*q]);
      a2p[2*q+1] = ffma2(sd, wq.y, a2p[2*q+1]);
    }
  }
  float a2[32];
  #pragma unroll
  for (int jp = 0; jp < 16; jp++){
    float lo, hi; unpk2(a2p[jp], lo, hi);
    a2[jp] = fmaxf(lo, 0.f); a2[jp+16] = fmaxf(hi, 0.f);
  }
  float o[4];
  #pragma unroll
  for (int j = 0; j < 4; j++){
    float acc = sb3[j];
    #pragma unroll
    for (int q = 0; q < 8; q++){
      float4 wv = sW3[j*8 + q];
      acc = fmaf(a2[4*q],   wv.x, acc);
      acc = fmaf(a2[4*q+1], wv.y, acc);
      acc = fmaf(a2[4*q+2], wv.z, acc);
      acc = fmaf(a2[4*q+3], wv.w, acc);
    }
    o[j] = acc;
  }
  ((float4*)out)[e] = make_float4(o[0], o[1], o[2], o[3]);
}

extern "C" void kernel_launch(void* const* d_in, const int* in_sizes, int n_in,
                              void* d_out, int out_size){
  (void)in_sizes; (void)n_in; (void)out_size;
  const float* x    = (const float*)d_in[0];
  const void*  ei   = d_in[1];
  const float* ea   = (const float*)d_in[2];
  const float* u    = (const float*)d_in[3];
  const float* Win  = (const float*)d_in[4];
  const float* eW1  = (const float*)d_in[6];
  const float* eb1  = (const float*)d_in[7];
  const float* eW2  = (const float*)d_in[8];
  const float* eb2  = (const float*)d_in[9];
  const float* msW  = (const float*)d_in[10];
  const float* msb  = (const float*)d_in[11];
  const float* Wih  = (const float*)d_in[12];
  const float* bih  = (const float*)d_in[13];
  const float* Whh  = (const float*)d_in[14];
  const float* bhh  = (const float*)d_in[15];
  const float* dW1  = (const float*)d_in[16];
  const float* db1  = (const float*)d_in[17];
  const float* dW2  = (const float*)d_in[18];
  const float* db2  = (const float*)d_in[19];
  const float* dW3  = (const float*)d_in[20];
  const float* db3  = (const float*)d_in[21];
  const float* bin  = (const float*)d_in[5];
  float* out = (float*)d_out;

  static int init_done = 0;
  static cudaStream_t s1;
  static cudaEvent_t evA, evB;
  if (!init_done){
    cudaFuncSetAttribute(k_gru, cudaFuncAttributeMaxDynamicSharedMemorySize, GRU_SMEM);
    cudaStreamCreateWithFlags(&s1, cudaStreamNonBlocking);
    cudaEventCreateWithFlags(&evA, cudaEventDisableTiming);
    cudaEventCreateWithFlags(&evB, cudaEventDisableTiming);
    init_done = 1;
  }

  // shared prologue on capture (default) stream
  k_detect<<<1, 256>>>((const int*)ei);
  k_zero<<<(NN + 255)/256, 256>>>();
  k_packw<<<(7328 + 255)/256, 256>>>(Wih, Whh, dW2, dW1);
  k_packw2<<<(2224 + 255)/256, 256>>>(msW, eW1, eb1, eW2, Win, bin, u);

  cudaEventRecord(evA, 0);
  cudaStreamWaitEvent(s1, evA, 0);

  const int GRID_W   = 1184;
  const int GRID_AGG = (NN*32 + 255)/256;
  const int GRID_GRU = 296;

  float *hA_p = nullptr, *hB_p = nullptr;
  cudaGetSymbolAddress((void**)&hA_p, g_hA);
  cudaGetSymbolAddress((void**)&hB_p, g_hB);

  // node chain on s1
  k_h2<<<(NN*H + 255)/256, 256, 0, s1>>>(x, Win);
  k_hm<<<GRID_W, 256, 0, s1>>>(hA_p, msb);
  cudaEventRecord(evB, s1);

  // edge chain on default stream
  k_prep<<<(MM + 255)/256, 256>>>(ei, ea, eb2);
  k_scan1<<<SCB, 256>>>();
  k_scan2<<<1, 256>>>();
  k_scan3<<<SCB, 256>>>();
  k_fill<<<(MM + 255)/256, 256>>>();

  cudaStreamWaitEvent(0, evB, 0);

  k_agg<<<GRID_AGG, 256>>>();
  k_gru<<<GRID_GRU, 256, GRU_SMEM>>>(hA_p, hB_p, bih, bhh);

  k_hm<<<GRID_W, 256>>>(hB_p, msb);
  k_agg<<<GRID_AGG, 256>>>();
  k_gru<<<GRID_GRU, 256, GRU_SMEM>>>(hB_p, hA_p, bih, bhh);

  k_hm<<<GRID_W, 256>>>(hA_p, msb);
  k_agg<<<GRID_AGG, 256>>>();
  k_gru<<<GRID_GRU, 256, GRU_SMEM>>>(hA_p, hB_p, bih, bhh);

  k_AB<<<GRID_W, 256>>>(hB_p, dW1, db1);
  k_dec<<<(MM + 255)/256, 256>>>(ea, out, db2, dW3, db3);
}